// round 9
// baseline (speedup 1.0000x reference)
#include <cuda_runtime.h>
#include <cuda_bf16.h>
#include <math.h>
#include <stdint.h>

// ---------------------------------------------------------------------------
// Problem constants
// ---------------------------------------------------------------------------
#define BATCH 4
#define C_DIM 1024
#define CI_DIM 512
#define T_DIM 16
#define H_DIM 28
#define W_DIM 28
#define NPOS (T_DIM * H_DIM * W_DIM)   // 12544
#define TP 8
#define HP 14
#define WP 14
#define MPOS (TP * HP * WP)            // 1568
#define MPAD 1664                      // 13 * 128 (zero-padded attention dim)

typedef __nv_bfloat16 bf16;

// ---------------------------------------------------------------------------
// Scratch (device globals; zero-initialized at module load — pad regions are
// never written and therefore stay zero across all graph replays)
// ---------------------------------------------------------------------------
__device__ bf16  d_xT  [(size_t)BATCH * NPOS * C_DIM];    // x^T  (B,N,C)  bf16
__device__ bf16  d_wbuf[(size_t)4 * CI_DIM * C_DIM];      // weights bf16 (th,ph,g,w)
__device__ bf16  d_theta[(size_t)BATCH * NPOS * CI_DIM];  // theta (B,N,Ci)
__device__ bf16  d_scr [(size_t)BATCH * NPOS * CI_DIM];   // conv scratch
__device__ bf16  d_phi [(size_t)BATCH * MPAD * CI_DIM];   // phi pooled, M-padded
__device__ bf16  d_gmc [(size_t)BATCH * MPOS * CI_DIM];   // g pooled (B,M,Ci)
__device__ bf16  d_gcm [(size_t)BATCH * CI_DIM * MPAD];   // g pooled^T, M-padded
__device__ float d_fbuf[(size_t)BATCH * NPOS * MPAD];     // logits fp32
__device__ bf16  d_pbuf[(size_t)BATCH * NPOS * MPAD];     // softmax probs bf16
__device__ bf16  d_ybuf[(size_t)BATCH * NPOS * CI_DIM];   // y (B,N,Ci)

// ---------------------------------------------------------------------------
// PTX helpers
// ---------------------------------------------------------------------------
__device__ __forceinline__ uint32_t smem_u32(const void* p) {
    return (uint32_t)__cvta_generic_to_shared(p);
}
__device__ __forceinline__ void ldmatrix_x4(uint32_t* r, uint32_t addr) {
    asm volatile("ldmatrix.sync.aligned.m8n8.x4.shared.b16 {%0,%1,%2,%3}, [%4];"
                 : "=r"(r[0]), "=r"(r[1]), "=r"(r[2]), "=r"(r[3]) : "r"(addr));
}
__device__ __forceinline__ void ldmatrix_x2(uint32_t* r, uint32_t addr) {
    asm volatile("ldmatrix.sync.aligned.m8n8.x2.shared.b16 {%0,%1}, [%2];"
                 : "=r"(r[0]), "=r"(r[1]) : "r"(addr));
}
__device__ __forceinline__ void mma_16816(float* c, const uint32_t* a, const uint32_t* b) {
    asm volatile("mma.sync.aligned.m16n8k16.row.col.f32.bf16.bf16.f32 "
                 "{%0,%1,%2,%3}, {%4,%5,%6,%7}, {%8,%9}, {%0,%1,%2,%3};"
                 : "+f"(c[0]), "+f"(c[1]), "+f"(c[2]), "+f"(c[3])
                 : "r"(a[0]), "r"(a[1]), "r"(a[2]), "r"(a[3]), "r"(b[0]), "r"(b[1]));
}
__device__ __forceinline__ void cp16(void* s, const void* g) {
    asm volatile("cp.async.cg.shared.global [%0], [%1], 16;"
                 :: "r"(smem_u32(s)), "l"(g));
}
#define CP_COMMIT asm volatile("cp.async.commit_group;")
#define CP_WAIT0  asm volatile("cp.async.wait_group 0;")
#define CP_WAIT1  asm volatile("cp.async.wait_group 1;")

// ---------------------------------------------------------------------------
// bf16 NT tensor-core GEMM: C(MxN) = A(MxK) * B(NxK)^T, K-contiguous inputs.
// Tile 128x128x32, 8 warps (2x4), m16n8k16 HMMA, cp.async double buffer.
// Requires M%128==0, N%128==0, K%32==0.
// EPI 0: plain   EPI 1: + colBias[col]
// EPI 2: out = resid + gamma[row]/sqrt(1+eps)*(acc + rowBias[row]) + beta[row]
// ---------------------------------------------------------------------------
#define SSTR 40  // smem row stride in bf16 (32 + 8 pad -> conflict-free LDSM)

template <int EPI, typename OutT>
__global__ void __launch_bounds__(256, 1)
mma_nt(const bf16* __restrict__ A, const bf16* __restrict__ B,
       OutT* __restrict__ C, int M, int N, int K,
       long sA, long sB, long sC,
       const float* __restrict__ colBias,
       const float* __restrict__ rowBias,
       const float* __restrict__ gamma,
       const float* __restrict__ beta,
       const float* __restrict__ resid, long sR) {
    __shared__ bf16 As[2][128 * SSTR];
    __shared__ bf16 Bs[2][128 * SSTR];
    A += (long)blockIdx.z * sA;
    B += (long)blockIdx.z * sB;
    C += (long)blockIdx.z * sC;
    const int m0 = blockIdx.y * 128;
    const int n0 = blockIdx.x * 128;
    const int tid = threadIdx.x;
    const int lane = tid & 31;
    const int warp = tid >> 5;
    const int wm = (warp & 1) * 64;   // warp row offset
    const int wn = (warp >> 1) * 32;  // warp col offset

    // global->smem staging map: 256 threads, each loads 2x16B per tile
    const int lrow = tid >> 1;
    const int lcol = (tid & 1) * 16;
    const bf16* gA = A + (long)(m0 + lrow) * K + lcol;
    const bf16* gB = B + (long)(n0 + lrow) * K + lcol;
    bf16* sA0 = &As[0][lrow * SSTR + lcol];
    bf16* sB0 = &Bs[0][lrow * SSTR + lcol];
    bf16* sA1 = &As[1][lrow * SSTR + lcol];
    bf16* sB1 = &Bs[1][lrow * SSTR + lcol];

    float acc[4][4][4] = {};

    const int nIter = K >> 5;
    cp16(sA0, gA); cp16(sA0 + 8, gA + 8);
    cp16(sB0, gB); cp16(sB0 + 8, gB + 8);
    CP_COMMIT;

    for (int it = 0; it < nIter; ++it) {
        const int buf = it & 1;
        if (it + 1 < nIter) {
            const long off = (long)(it + 1) * 32;
            bf16* dA = buf ? sA0 : sA1;
            bf16* dB = buf ? sB0 : sB1;
            cp16(dA, gA + off); cp16(dA + 8, gA + off + 8);
            cp16(dB, gB + off); cp16(dB + 8, gB + off + 8);
            CP_COMMIT;
            CP_WAIT1;
        } else {
            CP_WAIT0;
        }
        __syncthreads();
#pragma unroll
        for (int ks = 0; ks < 2; ++ks) {
            const int kb = ks * 16;
            uint32_t afr[4][4], bfr[4][2];
#pragma unroll
            for (int mi = 0; mi < 4; mi++)
                ldmatrix_x4(afr[mi], smem_u32(
                    &As[buf][(wm + mi * 16 + (lane & 15)) * SSTR + kb + (lane >> 4) * 8]));
#pragma unroll
            for (int ni = 0; ni < 4; ni++)
                ldmatrix_x2(bfr[ni], smem_u32(
                    &Bs[buf][(wn + ni * 8 + (lane & 7)) * SSTR + kb + ((lane >> 3) & 1) * 8]));
#pragma unroll
            for (int mi = 0; mi < 4; mi++)
#pragma unroll
                for (int ni = 0; ni < 4; ni++)
                    mma_16816(acc[mi][ni], afr[mi], bfr[ni]);
        }
        __syncthreads();
    }

    // epilogue
    const int tr = lane >> 2;
    const int tc = (lane & 3) * 2;
    const float bnscale = rsqrtf(1.0f + 1e-5f);
#pragma unroll
    for (int mi = 0; mi < 4; mi++) {
        const int r = m0 + wm + mi * 16 + tr;
#pragma unroll
        for (int ni = 0; ni < 4; ni++) {
            const int c = n0 + wn + ni * 8 + tc;
#pragma unroll
            for (int h = 0; h < 2; h++) {
                const int rr = r + h * 8;
                float v0 = acc[mi][ni][h * 2 + 0];
                float v1 = acc[mi][ni][h * 2 + 1];
                if (EPI == 1) {
                    v0 += colBias[c];
                    v1 += colBias[c + 1];
                } else if (EPI == 2) {
                    const float s = gamma[rr] * bnscale;
                    const float wb = rowBias[rr];
                    const float bt = beta[rr];
                    const float* rp = resid + (long)blockIdx.z * sR + (long)rr * N + c;
                    v0 = rp[0] + s * (v0 + wb) + bt;
                    v1 = rp[1] + s * (v1 + wb) + bt;
                }
                if constexpr (sizeof(OutT) == 2) {
                    __nv_bfloat162 p = __floats2bfloat162_rn(v0, v1);
                    *reinterpret_cast<__nv_bfloat162*>(
                        &((bf16*)C)[(long)rr * N + c]) = p;
                } else {
                    float2 p = make_float2(v0, v1);
                    *reinterpret_cast<float2*>(&((float*)C)[(long)rr * N + c]) = p;
                }
            }
        }
    }
}

// ---------------------------------------------------------------------------
// Tiled transpose with dtype conversion: in (R,Cc) -> out (Cc,R) [ldOut], per z
// ---------------------------------------------------------------------------
__device__ __forceinline__ float ld_as_f(const float* p) { return *p; }
__device__ __forceinline__ float ld_as_f(const bf16* p) { return __bfloat162float(*p); }
__device__ __forceinline__ void st_from_f(float* p, float v) { *p = v; }
__device__ __forceinline__ void st_from_f(bf16* p, float v) { *p = __float2bfloat16(v); }

template <typename TI, typename TO>
__global__ void transpose_k(const TI* __restrict__ in, TO* __restrict__ out,
                            int R, int Cc, int ldOut, long sIn, long sOut) {
    __shared__ float tile[32][33];
    const TI* inb = in + (long)blockIdx.z * sIn;
    TO* outb = out + (long)blockIdx.z * sOut;
    const int c0 = blockIdx.x * 32;
    const int r0 = blockIdx.y * 32;
    const int tx = threadIdx.x, ty = threadIdx.y;
#pragma unroll
    for (int i = 0; i < 32; i += 8)
        tile[ty + i][tx] = ld_as_f(&inb[(long)(r0 + ty + i) * Cc + c0 + tx]);
    __syncthreads();
#pragma unroll
    for (int i = 0; i < 32; i += 8)
        st_from_f(&outb[(long)(c0 + ty + i) * ldOut + r0 + tx], tile[tx][ty + i]);
}

// ---------------------------------------------------------------------------
// fp32 -> bf16 elementwise convert
// ---------------------------------------------------------------------------
__global__ void f2bf_k(const float* __restrict__ in, bf16* __restrict__ out, int n) {
    const int i = blockIdx.x * 256 + threadIdx.x;
    if (i < n) out[i] = __float2bfloat16(in[i]);
}

// ---------------------------------------------------------------------------
// 2x2x2 max pool (bf16): conv (B,NPOS,Ci) -> out (B,outRows,Ci), rows 0..MPOS-1
// ---------------------------------------------------------------------------
__global__ void pool_k(const bf16* __restrict__ conv, bf16* __restrict__ out,
                       int outRows) {
    const int ci = blockIdx.x * 256 + threadIdx.x;
    const int m = blockIdx.y;
    const int b = blockIdx.z;
    const int wp = m % WP;
    const int hp = (m / WP) % HP;
    const int tp = m / (WP * HP);
    const bf16* cb = conv + (long)b * NPOS * CI_DIM;
    const long n0 = (long)(2 * tp) * (H_DIM * W_DIM) + (long)(2 * hp) * W_DIM + 2 * wp;
    float mx = -INFINITY;
#pragma unroll
    for (int dt = 0; dt < 2; dt++)
#pragma unroll
        for (int dh = 0; dh < 2; dh++)
#pragma unroll
            for (int dw = 0; dw < 2; dw++) {
                long n = n0 + dt * (H_DIM * W_DIM) + dh * W_DIM + dw;
                mx = fmaxf(mx, __bfloat162float(cb[n * CI_DIM + ci]));
            }
    out[((long)b * outRows + m) * CI_DIM + ci] = __float2bfloat16(mx);
}

// ---------------------------------------------------------------------------
// Row softmax: fp32 logits (stride MPAD, MPOS valid) -> bf16 probs
// (writes exact zeros into the MPOS..MPAD pad columns)
// ---------------------------------------------------------------------------
__global__ void __launch_bounds__(256) softmax_rows(const float* __restrict__ f,
                                                    bf16* __restrict__ p) {
    const float* fr = f + (long)blockIdx.x * MPAD;
    bf16* pr = p + (long)blockIdx.x * MPAD;
    const int t = threadIdx.x;
    float v[7];
    int cnt = 0;
    float mx = -1e30f;
    for (int i = t; i < MPOS; i += 256) {
        v[cnt] = fr[i];
        mx = fmaxf(mx, v[cnt]);
        cnt++;
    }
    __shared__ float sred[8];
#pragma unroll
    for (int o = 16; o; o >>= 1) mx = fmaxf(mx, __shfl_xor_sync(0xffffffffu, mx, o));
    if ((t & 31) == 0) sred[t >> 5] = mx;
    __syncthreads();
    if (t < 32) {
        float m2 = (t < 8) ? sred[t] : -1e30f;
#pragma unroll
        for (int o = 4; o; o >>= 1) m2 = fmaxf(m2, __shfl_xor_sync(0xffffffffu, m2, o));
        if (t == 0) sred[0] = m2;
    }
    __syncthreads();
    mx = sred[0];
    float sum = 0.f;
    for (int j = 0; j < cnt; j++) {
        v[j] = __expf(v[j] - mx);
        sum += v[j];
    }
    __syncthreads();
#pragma unroll
    for (int o = 16; o; o >>= 1) sum += __shfl_xor_sync(0xffffffffu, sum, o);
    if ((t & 31) == 0) sred[t >> 5] = sum;
    __syncthreads();
    if (t < 32) {
        float s2 = (t < 8) ? sred[t] : 0.f;
#pragma unroll
        for (int o = 4; o; o >>= 1) s2 += __shfl_xor_sync(0xffffffffu, s2, o);
        if (t == 0) sred[0] = s2;
    }
    __syncthreads();
    const float inv = 1.0f / sred[0];
    int j = 0;
    for (int i = t; i < MPOS; i += 256) {
        pr[i] = __float2bfloat16(v[j] * inv);
        j++;
    }
    for (int i = MPOS + t; i < MPAD; i += 256) pr[i] = __float2bfloat16(0.f);
}

// ---------------------------------------------------------------------------
// Launch
// ---------------------------------------------------------------------------
extern "C" void kernel_launch(void* const* d_in, const int* in_sizes, int n_in,
                              void* d_out, int out_size) {
    (void)in_sizes; (void)n_in; (void)out_size;
    const float* x     = (const float*)d_in[0];
    const float* g_w   = (const float*)d_in[1];
    const float* g_b   = (const float*)d_in[2];
    const float* th_w  = (const float*)d_in[3];
    const float* th_b  = (const float*)d_in[4];
    const float* ph_w  = (const float*)d_in[5];
    const float* ph_b  = (const float*)d_in[6];
    const float* w_w   = (const float*)d_in[7];
    const float* w_b   = (const float*)d_in[8];
    const float* gamma = (const float*)d_in[9];
    const float* beta  = (const float*)d_in[10];
    float* out = (float*)d_out;

    bf16 *xT, *wbuf, *theta, *scr, *phi, *gmc, *gcm, *pbuf, *ybuf;
    float* fbuf;
    cudaGetSymbolAddress((void**)&xT, d_xT);
    cudaGetSymbolAddress((void**)&wbuf, d_wbuf);
    cudaGetSymbolAddress((void**)&theta, d_theta);
    cudaGetSymbolAddress((void**)&scr, d_scr);
    cudaGetSymbolAddress((void**)&phi, d_phi);
    cudaGetSymbolAddress((void**)&gmc, d_gmc);
    cudaGetSymbolAddress((void**)&gcm, d_gcm);
    cudaGetSymbolAddress((void**)&fbuf, d_fbuf);
    cudaGetSymbolAddress((void**)&pbuf, d_pbuf);
    cudaGetSymbolAddress((void**)&ybuf, d_ybuf);

    bf16* th_wb = wbuf;                         // (Ci,C)
    bf16* ph_wb = wbuf + (size_t)CI_DIM * C_DIM;
    bf16* g_wb  = wbuf + (size_t)2 * CI_DIM * C_DIM;
    bf16* w_wb  = wbuf + (size_t)3 * CI_DIM * C_DIM;  // (C,Ci)

    const long sX  = (long)C_DIM * NPOS;
    const long sXT = (long)NPOS * C_DIM;
    const long sTH = (long)NPOS * CI_DIM;
    const long sPH = (long)MPAD * CI_DIM;
    const long sGC = (long)CI_DIM * MPAD;
    const long sF  = (long)NPOS * MPAD;

    const int nw = CI_DIM * C_DIM;
    // weights -> bf16
    f2bf_k<<<(nw + 255) / 256, 256>>>(th_w, th_wb, nw);
    f2bf_k<<<(nw + 255) / 256, 256>>>(ph_w, ph_wb, nw);
    f2bf_k<<<(nw + 255) / 256, 256>>>(g_w, g_wb, nw);
    f2bf_k<<<(nw + 255) / 256, 256>>>(w_w, w_wb, nw);

    // 1) x (B,C,N) -> xT bf16 (B,N,C)
    transpose_k<float, bf16><<<dim3(NPOS / 32, C_DIM / 32, BATCH), dim3(32, 8)>>>(
        x, xT, C_DIM, NPOS, C_DIM, sX, sXT);

    const dim3 gConv(CI_DIM / 128, NPOS / 128, BATCH);

    // 2) theta conv -> theta bf16 (N,Ci)
    mma_nt<1, bf16><<<gConv, 256>>>(xT, th_wb, theta, NPOS, CI_DIM, C_DIM,
                                    sXT, 0, sTH, th_b, nullptr, nullptr, nullptr,
                                    nullptr, 0);
    // 3) g conv -> scr, pool -> gmc (M,Ci), transpose -> gcm (Ci,Mpad)
    mma_nt<1, bf16><<<gConv, 256>>>(xT, g_wb, scr, NPOS, CI_DIM, C_DIM,
                                    sXT, 0, sTH, g_b, nullptr, nullptr, nullptr,
                                    nullptr, 0);
    pool_k<<<dim3(CI_DIM / 256, MPOS, BATCH), 256>>>(scr, gmc, MPOS);
    transpose_k<bf16, bf16><<<dim3(CI_DIM / 32, MPOS / 32, BATCH), dim3(32, 8)>>>(
        gmc, gcm, MPOS, CI_DIM, MPAD, (long)MPOS * CI_DIM, sGC);
    // 4) phi conv -> scr, pool -> phi (Mpad,Ci) (pad rows stay zero)
    mma_nt<1, bf16><<<gConv, 256>>>(xT, ph_wb, scr, NPOS, CI_DIM, C_DIM,
                                    sXT, 0, sTH, ph_b, nullptr, nullptr, nullptr,
                                    nullptr, 0);
    pool_k<<<dim3(CI_DIM / 256, MPOS, BATCH), 256>>>(scr, phi, MPAD);

    // 5) f = theta @ phi^T : (N,Ci)x(Mpad,Ci)^T -> fp32 (N,Mpad)
    mma_nt<0, float><<<dim3(MPAD / 128, NPOS / 128, BATCH), 256>>>(
        theta, phi, fbuf, NPOS, MPAD, CI_DIM,
        sTH, sPH, sF, nullptr, nullptr, nullptr, nullptr, nullptr, 0);

    // 6) softmax rows (fp32 -> bf16 probs, zeros in pads)
    softmax_rows<<<BATCH * NPOS, 256>>>(fbuf, pbuf);

    // 7) y = p @ g : (N,Mpad)x(Ci,Mpad)^T -> bf16 (N,Ci)
    mma_nt<0, bf16><<<dim3(CI_DIM / 128, NPOS / 128, BATCH), 256>>>(
        pbuf, gcm, ybuf, NPOS, CI_DIM, MPAD,
        sF, sGC, sTH, nullptr, nullptr, nullptr, nullptr, nullptr, 0);

    // 8) out(C,N) = x + scale*(w_w @ y^T + w_b) + beta
    mma_nt<2, float><<<dim3(NPOS / 128, C_DIM / 128, BATCH), 256>>>(
        w_wb, ybuf, out, C_DIM, NPOS, CI_DIM,
        0, sTH, sX, nullptr, w_b, gamma, beta, x, sX);
}

// round 10
// speedup vs baseline: 1.0020x; 1.0020x over previous
#include <cuda_runtime.h>
#include <cuda_bf16.h>
#include <math.h>
#include <stdint.h>

// ---------------------------------------------------------------------------
// Problem constants
// ---------------------------------------------------------------------------
#define BATCH 4
#define C_DIM 1024
#define CI_DIM 512
#define T_DIM 16
#define H_DIM 28
#define W_DIM 28
#define NPOS (T_DIM * H_DIM * W_DIM)   // 12544
#define TP 8
#define HP 14
#define WP 14
#define MPOS (TP * HP * WP)            // 1568
#define MPAD 1664                      // 13 * 128 (zero-padded attention dim)

typedef __nv_bfloat16 bf16;

// ---------------------------------------------------------------------------
// Scratch (device globals; zero-initialized at module load — pad regions are
// never written and therefore stay zero across all graph replays)
// ---------------------------------------------------------------------------
__device__ bf16  d_xT  [(size_t)BATCH * NPOS * C_DIM];    // x^T  (B,N,C)  bf16
__device__ bf16  d_wbuf[(size_t)4 * CI_DIM * C_DIM];      // weights bf16 (th,ph,g,w)
__device__ bf16  d_theta[(size_t)BATCH * NPOS * CI_DIM];  // theta (B,N,Ci)
__device__ bf16  d_scr [(size_t)BATCH * NPOS * CI_DIM];   // conv scratch
__device__ bf16  d_phi [(size_t)BATCH * MPAD * CI_DIM];   // phi pooled, M-padded
__device__ bf16  d_gmc [(size_t)BATCH * MPOS * CI_DIM];   // g pooled (B,M,Ci)
__device__ bf16  d_gcm [(size_t)BATCH * CI_DIM * MPAD];   // g pooled^T, M-padded
__device__ float d_fbuf[(size_t)BATCH * NPOS * MPAD];     // logits fp32
__device__ bf16  d_pbuf[(size_t)BATCH * NPOS * MPAD];     // softmax probs bf16
__device__ bf16  d_ybuf[(size_t)BATCH * NPOS * CI_DIM];   // y (B,N,Ci)

// ---------------------------------------------------------------------------
// PTX helpers
// ---------------------------------------------------------------------------
__device__ __forceinline__ uint32_t smem_u32(const void* p) {
    return (uint32_t)__cvta_generic_to_shared(p);
}
__device__ __forceinline__ void ldmatrix_x4(uint32_t* r, uint32_t addr) {
    asm volatile("ldmatrix.sync.aligned.m8n8.x4.shared.b16 {%0,%1,%2,%3}, [%4];"
                 : "=r"(r[0]), "=r"(r[1]), "=r"(r[2]), "=r"(r[3]) : "r"(addr));
}
__device__ __forceinline__ void ldmatrix_x2(uint32_t* r, uint32_t addr) {
    asm volatile("ldmatrix.sync.aligned.m8n8.x2.shared.b16 {%0,%1}, [%2];"
                 : "=r"(r[0]), "=r"(r[1]) : "r"(addr));
}
__device__ __forceinline__ void mma_16816(float* c, const uint32_t* a, const uint32_t* b) {
    asm volatile("mma.sync.aligned.m16n8k16.row.col.f32.bf16.bf16.f32 "
                 "{%0,%1,%2,%3}, {%4,%5,%6,%7}, {%8,%9}, {%0,%1,%2,%3};"
                 : "+f"(c[0]), "+f"(c[1]), "+f"(c[2]), "+f"(c[3])
                 : "r"(a[0]), "r"(a[1]), "r"(a[2]), "r"(a[3]), "r"(b[0]), "r"(b[1]));
}
__device__ __forceinline__ void cp16(void* s, const void* g) {
    asm volatile("cp.async.cg.shared.global [%0], [%1], 16;"
                 :: "r"(smem_u32(s)), "l"(g));
}
#define CP_COMMIT asm volatile("cp.async.commit_group;")
#define CP_WAIT0  asm volatile("cp.async.wait_group 0;")
#define CP_WAIT1  asm volatile("cp.async.wait_group 1;")

// ---------------------------------------------------------------------------
// bf16 NT tensor-core GEMM: C(MxN) = A(MxK) * B(NxK)^T, K-contiguous inputs.
// Tile 128x128x32, 8 warps (2x4), m16n8k16 HMMA, cp.async double buffer.
// Requires M%128==0, N%128==0, K%32==0.
// EPI 0: plain   EPI 1: + colBias[col]
// EPI 2: out = resid + gamma[row]/sqrt(1+eps)*(acc + rowBias[row]) + beta[row]
// ---------------------------------------------------------------------------
#define SSTR 40  // smem row stride in bf16 (32 + 8 pad -> conflict-free LDSM)

template <int EPI, typename OutT>
__global__ void __launch_bounds__(256, 1)
mma_nt(const bf16* __restrict__ A, const bf16* __restrict__ B,
       OutT* __restrict__ C, int M, int N, int K,
       long sA, long sB, long sC,
       const float* __restrict__ colBias,
       const float* __restrict__ rowBias,
       const float* __restrict__ gamma,
       const float* __restrict__ beta,
       const float* __restrict__ resid, long sR) {
    __shared__ bf16 As[2][128 * SSTR];
    __shared__ bf16 Bs[2][128 * SSTR];
    A += (long)blockIdx.z * sA;
    B += (long)blockIdx.z * sB;
    C += (long)blockIdx.z * sC;
    const int m0 = blockIdx.y * 128;
    const int n0 = blockIdx.x * 128;
    const int tid = threadIdx.x;
    const int lane = tid & 31;
    const int warp = tid >> 5;
    const int wm = (warp & 1) * 64;   // warp row offset
    const int wn = (warp >> 1) * 32;  // warp col offset

    // global->smem staging map: 256 threads, each loads 2x16B per tile
    const int lrow = tid >> 1;
    const int lcol = (tid & 1) * 16;
    const bf16* gA = A + (long)(m0 + lrow) * K + lcol;
    const bf16* gB = B + (long)(n0 + lrow) * K + lcol;
    bf16* sA0 = &As[0][lrow * SSTR + lcol];
    bf16* sB0 = &Bs[0][lrow * SSTR + lcol];
    bf16* sA1 = &As[1][lrow * SSTR + lcol];
    bf16* sB1 = &Bs[1][lrow * SSTR + lcol];

    float acc[4][4][4] = {};

    const int nIter = K >> 5;
    cp16(sA0, gA); cp16(sA0 + 8, gA + 8);
    cp16(sB0, gB); cp16(sB0 + 8, gB + 8);
    CP_COMMIT;

    for (int it = 0; it < nIter; ++it) {
        const int buf = it & 1;
        if (it + 1 < nIter) {
            const long off = (long)(it + 1) * 32;
            bf16* dA = buf ? sA0 : sA1;
            bf16* dB = buf ? sB0 : sB1;
            cp16(dA, gA + off); cp16(dA + 8, gA + off + 8);
            cp16(dB, gB + off); cp16(dB + 8, gB + off + 8);
            CP_COMMIT;
            CP_WAIT1;
        } else {
            CP_WAIT0;
        }
        __syncthreads();
#pragma unroll
        for (int ks = 0; ks < 2; ++ks) {
            const int kb = ks * 16;
            uint32_t afr[4][4], bfr[4][2];
#pragma unroll
            for (int mi = 0; mi < 4; mi++)
                ldmatrix_x4(afr[mi], smem_u32(
                    &As[buf][(wm + mi * 16 + (lane & 15)) * SSTR + kb + (lane >> 4) * 8]));
#pragma unroll
            for (int ni = 0; ni < 4; ni++)
                ldmatrix_x2(bfr[ni], smem_u32(
                    &Bs[buf][(wn + ni * 8 + (lane & 7)) * SSTR + kb + ((lane >> 3) & 1) * 8]));
#pragma unroll
            for (int mi = 0; mi < 4; mi++)
#pragma unroll
                for (int ni = 0; ni < 4; ni++)
                    mma_16816(acc[mi][ni], afr[mi], bfr[ni]);
        }
        __syncthreads();
    }

    // epilogue
    const int tr = lane >> 2;
    const int tc = (lane & 3) * 2;
    const float bnscale = rsqrtf(1.0f + 1e-5f);
#pragma unroll
    for (int mi = 0; mi < 4; mi++) {
        const int r = m0 + wm + mi * 16 + tr;
#pragma unroll
        for (int ni = 0; ni < 4; ni++) {
            const int c = n0 + wn + ni * 8 + tc;
#pragma unroll
            for (int h = 0; h < 2; h++) {
                const int rr = r + h * 8;
                float v0 = acc[mi][ni][h * 2 + 0];
                float v1 = acc[mi][ni][h * 2 + 1];
                if (EPI == 1) {
                    v0 += colBias[c];
                    v1 += colBias[c + 1];
                } else if (EPI == 2) {
                    const float s = gamma[rr] * bnscale;
                    const float wb = rowBias[rr];
                    const float bt = beta[rr];
                    const float* rp = resid + (long)blockIdx.z * sR + (long)rr * N + c;
                    v0 = rp[0] + s * (v0 + wb) + bt;
                    v1 = rp[1] + s * (v1 + wb) + bt;
                }
                if constexpr (sizeof(OutT) == 2) {
                    __nv_bfloat162 p = __floats2bfloat162_rn(v0, v1);
                    *reinterpret_cast<__nv_bfloat162*>(
                        &((bf16*)C)[(long)rr * N + c]) = p;
                } else {
                    float2 p = make_float2(v0, v1);
                    *reinterpret_cast<float2*>(&((float*)C)[(long)rr * N + c]) = p;
                }
            }
        }
    }
}

// ---------------------------------------------------------------------------
// Tiled transpose with dtype conversion: in (R,Cc) -> out (Cc,R) [ldOut], per z
// ---------------------------------------------------------------------------
__device__ __forceinline__ float ld_as_f(const float* p) { return *p; }
__device__ __forceinline__ float ld_as_f(const bf16* p) { return __bfloat162float(*p); }
__device__ __forceinline__ void st_from_f(float* p, float v) { *p = v; }
__device__ __forceinline__ void st_from_f(bf16* p, float v) { *p = __float2bfloat16(v); }

template <typename TI, typename TO>
__global__ void transpose_k(const TI* __restrict__ in, TO* __restrict__ out,
                            int R, int Cc, int ldOut, long sIn, long sOut) {
    __shared__ float tile[32][33];
    const TI* inb = in + (long)blockIdx.z * sIn;
    TO* outb = out + (long)blockIdx.z * sOut;
    const int c0 = blockIdx.x * 32;
    const int r0 = blockIdx.y * 32;
    const int tx = threadIdx.x, ty = threadIdx.y;
#pragma unroll
    for (int i = 0; i < 32; i += 8)
        tile[ty + i][tx] = ld_as_f(&inb[(long)(r0 + ty + i) * Cc + c0 + tx]);
    __syncthreads();
#pragma unroll
    for (int i = 0; i < 32; i += 8)
        st_from_f(&outb[(long)(c0 + ty + i) * ldOut + r0 + tx], tile[tx][ty + i]);
}

// ---------------------------------------------------------------------------
// fp32 -> bf16 elementwise convert
// ---------------------------------------------------------------------------
__global__ void f2bf_k(const float* __restrict__ in, bf16* __restrict__ out, int n) {
    const int i = blockIdx.x * 256 + threadIdx.x;
    if (i < n) out[i] = __float2bfloat16(in[i]);
}

// ---------------------------------------------------------------------------
// 2x2x2 max pool (bf16): conv (B,NPOS,Ci) -> out (B,outRows,Ci), rows 0..MPOS-1
// ---------------------------------------------------------------------------
__global__ void pool_k(const bf16* __restrict__ conv, bf16* __restrict__ out,
                       int outRows) {
    const int ci = blockIdx.x * 256 + threadIdx.x;
    const int m = blockIdx.y;
    const int b = blockIdx.z;
    const int wp = m % WP;
    const int hp = (m / WP) % HP;
    const int tp = m / (WP * HP);
    const bf16* cb = conv + (long)b * NPOS * CI_DIM;
    const long n0 = (long)(2 * tp) * (H_DIM * W_DIM) + (long)(2 * hp) * W_DIM + 2 * wp;
    float mx = -INFINITY;
#pragma unroll
    for (int dt = 0; dt < 2; dt++)
#pragma unroll
        for (int dh = 0; dh < 2; dh++)
#pragma unroll
            for (int dw = 0; dw < 2; dw++) {
                long n = n0 + dt * (H_DIM * W_DIM) + dh * W_DIM + dw;
                mx = fmaxf(mx, __bfloat162float(cb[n * CI_DIM + ci]));
            }
    out[((long)b * outRows + m) * CI_DIM + ci] = __float2bfloat16(mx);
}

// ---------------------------------------------------------------------------
// Row softmax: fp32 logits (stride MPAD, MPOS valid) -> bf16 probs
// (writes exact zeros into the MPOS..MPAD pad columns)
// ---------------------------------------------------------------------------
__global__ void __launch_bounds__(256) softmax_rows(const float* __restrict__ f,
                                                    bf16* __restrict__ p) {
    const float* fr = f + (long)blockIdx.x * MPAD;
    bf16* pr = p + (long)blockIdx.x * MPAD;
    const int t = threadIdx.x;
    float v[7];
    int cnt = 0;
    float mx = -1e30f;
    for (int i = t; i < MPOS; i += 256) {
        v[cnt] = fr[i];
        mx = fmaxf(mx, v[cnt]);
        cnt++;
    }
    __shared__ float sred[8];
#pragma unroll
    for (int o = 16; o; o >>= 1) mx = fmaxf(mx, __shfl_xor_sync(0xffffffffu, mx, o));
    if ((t & 31) == 0) sred[t >> 5] = mx;
    __syncthreads();
    if (t < 32) {
        float m2 = (t < 8) ? sred[t] : -1e30f;
#pragma unroll
        for (int o = 4; o; o >>= 1) m2 = fmaxf(m2, __shfl_xor_sync(0xffffffffu, m2, o));
        if (t == 0) sred[0] = m2;
    }
    __syncthreads();
    mx = sred[0];
    float sum = 0.f;
    for (int j = 0; j < cnt; j++) {
        v[j] = __expf(v[j] - mx);
        sum += v[j];
    }
    __syncthreads();
#pragma unroll
    for (int o = 16; o; o >>= 1) sum += __shfl_xor_sync(0xffffffffu, sum, o);
    if ((t & 31) == 0) sred[t >> 5] = sum;
    __syncthreads();
    if (t < 32) {
        float s2 = (t < 8) ? sred[t] : 0.f;
#pragma unroll
        for (int o = 4; o; o >>= 1) s2 += __shfl_xor_sync(0xffffffffu, s2, o);
        if (t == 0) sred[0] = s2;
    }
    __syncthreads();
    const float inv = 1.0f / sred[0];
    int j = 0;
    for (int i = t; i < MPOS; i += 256) {
        pr[i] = __float2bfloat16(v[j] * inv);
        j++;
    }
    for (int i = MPOS + t; i < MPAD; i += 256) pr[i] = __float2bfloat16(0.f);
}

// ---------------------------------------------------------------------------
// Launch
// ---------------------------------------------------------------------------
extern "C" void kernel_launch(void* const* d_in, const int* in_sizes, int n_in,
                              void* d_out, int out_size) {
    (void)in_sizes; (void)n_in; (void)out_size;
    const float* x     = (const float*)d_in[0];
    const float* g_w   = (const float*)d_in[1];
    const float* g_b   = (const float*)d_in[2];
    const float* th_w  = (const float*)d_in[3];
    const float* th_b  = (const float*)d_in[4];
    const float* ph_w  = (const float*)d_in[5];
    const float* ph_b  = (const float*)d_in[6];
    const float* w_w   = (const float*)d_in[7];
    const float* w_b   = (const float*)d_in[8];
    const float* gamma = (const float*)d_in[9];
    const float* beta  = (const float*)d_in[10];
    float* out = (float*)d_out;

    bf16 *xT, *wbuf, *theta, *scr, *phi, *gmc, *gcm, *pbuf, *ybuf;
    float* fbuf;
    cudaGetSymbolAddress((void**)&xT, d_xT);
    cudaGetSymbolAddress((void**)&wbuf, d_wbuf);
    cudaGetSymbolAddress((void**)&theta, d_theta);
    cudaGetSymbolAddress((void**)&scr, d_scr);
    cudaGetSymbolAddress((void**)&phi, d_phi);
    cudaGetSymbolAddress((void**)&gmc, d_gmc);
    cudaGetSymbolAddress((void**)&gcm, d_gcm);
    cudaGetSymbolAddress((void**)&fbuf, d_fbuf);
    cudaGetSymbolAddress((void**)&pbuf, d_pbuf);
    cudaGetSymbolAddress((void**)&ybuf, d_ybuf);

    bf16* th_wb = wbuf;                         // (Ci,C)
    bf16* ph_wb = wbuf + (size_t)CI_DIM * C_DIM;
    bf16* g_wb  = wbuf + (size_t)2 * CI_DIM * C_DIM;
    bf16* w_wb  = wbuf + (size_t)3 * CI_DIM * C_DIM;  // (C,Ci)

    const long sX  = (long)C_DIM * NPOS;
    const long sXT = (long)NPOS * C_DIM;
    const long sTH = (long)NPOS * CI_DIM;
    const long sPH = (long)MPAD * CI_DIM;
    const long sGC = (long)CI_DIM * MPAD;
    const long sF  = (long)NPOS * MPAD;

    const int nw = CI_DIM * C_DIM;
    // weights -> bf16
    f2bf_k<<<(nw + 255) / 256, 256>>>(th_w, th_wb, nw);
    f2bf_k<<<(nw + 255) / 256, 256>>>(ph_w, ph_wb, nw);
    f2bf_k<<<(nw + 255) / 256, 256>>>(g_w, g_wb, nw);
    f2bf_k<<<(nw + 255) / 256, 256>>>(w_w, w_wb, nw);

    // 1) x (B,C,N) -> xT bf16 (B,N,C)
    transpose_k<float, bf16><<<dim3(NPOS / 32, C_DIM / 32, BATCH), dim3(32, 8)>>>(
        x, xT, C_DIM, NPOS, C_DIM, sX, sXT);

    const dim3 gConv(CI_DIM / 128, NPOS / 128, BATCH);

    // 2) theta conv -> theta bf16 (N,Ci)
    mma_nt<1, bf16><<<gConv, 256>>>(xT, th_wb, theta, NPOS, CI_DIM, C_DIM,
                                    sXT, 0, sTH, th_b, nullptr, nullptr, nullptr,
                                    nullptr, 0);
    // 3) g conv -> scr, pool -> gmc (M,Ci), transpose -> gcm (Ci,Mpad)
    mma_nt<1, bf16><<<gConv, 256>>>(xT, g_wb, scr, NPOS, CI_DIM, C_DIM,
                                    sXT, 0, sTH, g_b, nullptr, nullptr, nullptr,
                                    nullptr, 0);
    pool_k<<<dim3(CI_DIM / 256, MPOS, BATCH), 256>>>(scr, gmc, MPOS);
    transpose_k<bf16, bf16><<<dim3(CI_DIM / 32, MPOS / 32, BATCH), dim3(32, 8)>>>(
        gmc, gcm, MPOS, CI_DIM, MPAD, (long)MPOS * CI_DIM, sGC);
    // 4) phi conv -> scr, pool -> phi (Mpad,Ci) (pad rows stay zero)
    mma_nt<1, bf16><<<gConv, 256>>>(xT, ph_wb, scr, NPOS, CI_DIM, C_DIM,
                                    sXT, 0, sTH, ph_b, nullptr, nullptr, nullptr,
                                    nullptr, 0);
    pool_k<<<dim3(CI_DIM / 256, MPOS, BATCH), 256>>>(scr, phi, MPAD);

    // 5) f = theta @ phi^T : (N,Ci)x(Mpad,Ci)^T -> fp32 (N,Mpad)
    mma_nt<0, float><<<dim3(MPAD / 128, NPOS / 128, BATCH), 256>>>(
        theta, phi, fbuf, NPOS, MPAD, CI_DIM,
        sTH, sPH, sF, nullptr, nullptr, nullptr, nullptr, nullptr, 0);

    // 6) softmax rows (fp32 -> bf16 probs, zeros in pads)
    softmax_rows<<<BATCH * NPOS, 256>>>(fbuf, pbuf);

    // 7) y = p @ g : (N,Mpad)x(Ci,Mpad)^T -> bf16 (N,Ci)
    mma_nt<0, bf16><<<dim3(CI_DIM / 128, NPOS / 128, BATCH), 256>>>(
        pbuf, gcm, ybuf, NPOS, CI_DIM, MPAD,
        sF, sGC, sTH, nullptr, nullptr, nullptr, nullptr, nullptr, 0);

    // 8) out(C,N) = x + scale*(w_w @ y^T + w_b) + beta
    mma_nt<2, float><<<dim3(NPOS / 128, C_DIM / 128, BATCH), 256>>>(
        w_wb, ybuf, out, C_DIM, NPOS, CI_DIM,
        0, sTH, sX, nullptr, w_b, gamma, beta, x, sX);
}

// round 12
// speedup vs baseline: 1.6196x; 1.6164x over previous
#include <cuda_runtime.h>
#include <cuda_bf16.h>
#include <math.h>
#include <stdint.h>

// ---------------------------------------------------------------------------
// Problem constants
// ---------------------------------------------------------------------------
#define BATCH 4
#define C_DIM 1024
#define CI_DIM 512
#define T_DIM 16
#define H_DIM 28
#define W_DIM 28
#define NPOS (T_DIM * H_DIM * W_DIM)   // 12544
#define TP 8
#define HP 14
#define WP 14
#define MPOS (TP * HP * WP)            // 1568
#define MPAD 1664                      // 13 * 128 (zero-padded attention dim)

typedef __nv_bfloat16 bf16;

// ---------------------------------------------------------------------------
// Scratch (device globals; zero-initialized at load — pad regions never written)
// ---------------------------------------------------------------------------
__device__ bf16  d_xT  [(size_t)BATCH * NPOS * C_DIM];    // x^T  (B,N,C)
__device__ bf16  d_wbuf[(size_t)4 * CI_DIM * C_DIM];      // bf16 weights
__device__ bf16  d_theta[(size_t)BATCH * NPOS * CI_DIM];  // theta (B,N,Ci)
__device__ bf16  d_scr [(size_t)BATCH * NPOS * CI_DIM];   // conv scratch
__device__ bf16  d_phi [(size_t)BATCH * MPAD * CI_DIM];   // phi pooled, M-padded
__device__ bf16  d_gmc [(size_t)BATCH * MPOS * CI_DIM];   // g pooled (B,M,Ci)
__device__ bf16  d_gcm [(size_t)BATCH * CI_DIM * MPAD];   // g pooled^T, M-padded
__device__ bf16  d_fbuf[(size_t)BATCH * NPOS * MPAD];     // logits->probs bf16
__device__ bf16  d_ybuf[(size_t)BATCH * NPOS * CI_DIM];   // y (B,N,Ci)

// ---------------------------------------------------------------------------
// PTX helpers (legacy tensor path: ldmatrix + mma.sync — compute_103-safe)
// ---------------------------------------------------------------------------
__device__ __forceinline__ uint32_t smem_u32(const void* p) {
    return (uint32_t)__cvta_generic_to_shared(p);
}
__device__ __forceinline__ void ldmatrix_x4(uint32_t* r, uint32_t addr) {
    asm volatile("ldmatrix.sync.aligned.m8n8.x4.shared.b16 {%0,%1,%2,%3}, [%4];"
                 : "=r"(r[0]), "=r"(r[1]), "=r"(r[2]), "=r"(r[3]) : "r"(addr));
}
__device__ __forceinline__ void ldmatrix_x2(uint32_t* r, uint32_t addr) {
    asm volatile("ldmatrix.sync.aligned.m8n8.x2.shared.b16 {%0,%1}, [%2];"
                 : "=r"(r[0]), "=r"(r[1]) : "r"(addr));
}
__device__ __forceinline__ void mma_16816(float* c, const uint32_t* a, const uint32_t* b) {
    asm volatile("mma.sync.aligned.m16n8k16.row.col.f32.bf16.bf16.f32 "
                 "{%0,%1,%2,%3}, {%4,%5,%6,%7}, {%8,%9}, {%0,%1,%2,%3};"
                 : "+f"(c[0]), "+f"(c[1]), "+f"(c[2]), "+f"(c[3])
                 : "r"(a[0]), "r"(a[1]), "r"(a[2]), "r"(a[3]), "r"(b[0]), "r"(b[1]));
}
__device__ __forceinline__ void cp16(uint32_t s, const void* g) {
    asm volatile("cp.async.cg.shared.global [%0], [%1], 16;" :: "r"(s), "l"(g));
}
#define CP_COMMIT asm volatile("cp.async.commit_group;")
#define CP_WAIT0  asm volatile("cp.async.wait_group 0;")
#define CP_WAIT1  asm volatile("cp.async.wait_group 1;")

// ---------------------------------------------------------------------------
// bf16 NT tensor-core GEMM: C(MxN) = A(MxK) * B(NxK)^T, K-contiguous inputs.
// Tile 128x128, K chunks of 64, 3-stage cp.async ring (one __syncthreads per
// chunk), padded-stride smem (144B rows: conflict-free STS.128 + ldmatrix).
// Requires M%128==0, N%128==0, K%64==0, K>=128.
// EPI 0: plain   EPI 1: + colBias[col]
// EPI 2: out = resid + gamma[row]/sqrt(1+eps)*(acc + rowBias[row]) + beta[row]
// ---------------------------------------------------------------------------
#define ROWB 144u                 // smem row stride bytes (64*2 + 16 pad)
#define MATB (128u * ROWB)        // 18432 bytes per matrix per stage
#define STGB (2u * MATB)          // 36864 bytes per stage (A + B)
#define SMEM_MMA (3 * (int)STGB)  // 110592 bytes

template <int EPI, typename OutT>
__global__ void __launch_bounds__(256, 2)
mma_nt(const bf16* __restrict__ A, const bf16* __restrict__ B,
       OutT* __restrict__ C, int M, int N, int K,
       long sA, long sB, long sC,
       const float* __restrict__ colBias,
       const float* __restrict__ rowBias,
       const float* __restrict__ gamma,
       const float* __restrict__ beta,
       const float* __restrict__ resid, long sR) {
    extern __shared__ char smem[];
    const uint32_t sbase = smem_u32(smem);
    const int tid = threadIdx.x;
    const int lane = tid & 31;
    const int warp = tid >> 5;
    const int z = blockIdx.z;
    const int m0 = blockIdx.y * 128;
    const int n0 = blockIdx.x * 128;
    const int wm = (warp & 1) * 64;   // warp row offset
    const int wn = (warp >> 1) * 32;  // warp col offset

    const char* gA = (const char*)(A + (long)z * sA) + (long)m0 * K * 2;
    const char* gB = (const char*)(B + (long)z * sB) + (long)n0 * K * 2;
    const long strK = (long)K * 2;
    const int nCh = K >> 6;

    // staging map: chunk = 128 rows x 128B per matrix = 1024 x 16B; 256 thr x 4
    int srow[4];
    uint32_t soff[4];
#pragma unroll
    for (int t = 0; t < 4; t++) {
        const int idx = tid + t * 256;
        srow[t] = idx >> 3;
        soff[t] = (uint32_t)(idx >> 3) * ROWB + (uint32_t)(idx & 7) * 16u;
    }

#define LOAD_CHUNK(buf, ch)                                                   \
    {                                                                         \
        const long cb = (long)(ch) << 7;                                      \
        const uint32_t s0 = sbase + (uint32_t)(buf) * STGB;                   \
        _Pragma("unroll") for (int t = 0; t < 4; t++) {                       \
            const long go = (long)srow[t] * strK + cb + ((soff[t] % ROWB));   \
            cp16(s0 + soff[t], gA + go);                                      \
            cp16(s0 + MATB + soff[t], gB + go);                               \
        }                                                                     \
        CP_COMMIT;                                                            \
    }

    float acc[4][4][4] = {};

    LOAD_CHUNK(0, 0);
    LOAD_CHUNK(1, 1);

    for (int c = 0; c < nCh; ++c) {
        if (c + 1 < nCh) { CP_WAIT1; } else { CP_WAIT0; }
        __syncthreads();
        if (c + 2 < nCh) {
            const int nb = (c + 2) % 3;
            LOAD_CHUNK(nb, c + 2);
        }
        const uint32_t sa = sbase + (uint32_t)(c % 3) * STGB;
        const uint32_t sb = sa + MATB;
#pragma unroll
        for (int ks = 0; ks < 4; ++ks) {
            uint32_t afr[4][4], bfr[4][2];
#pragma unroll
            for (int mi = 0; mi < 4; mi++)
                ldmatrix_x4(afr[mi],
                    sa + (uint32_t)(wm + mi * 16 + (lane & 15)) * ROWB +
                         (uint32_t)ks * 32u + (uint32_t)(lane >> 4) * 16u);
#pragma unroll
            for (int ni = 0; ni < 4; ni++)
                ldmatrix_x2(bfr[ni],
                    sb + (uint32_t)(wn + ni * 8 + (lane & 7)) * ROWB +
                         (uint32_t)ks * 32u + (uint32_t)((lane >> 3) & 1) * 16u);
#pragma unroll
            for (int mi = 0; mi < 4; mi++)
#pragma unroll
                for (int ni = 0; ni < 4; ni++)
                    mma_16816(acc[mi][ni], afr[mi], bfr[ni]);
        }
    }

    // ---- epilogue ----
    const int tr = lane >> 2;
    const int tc = (lane & 3) * 2;
    const float bnscale = rsqrtf(1.0f + 1e-5f);
#pragma unroll
    for (int mi = 0; mi < 4; mi++) {
        const int r = m0 + wm + mi * 16 + tr;
#pragma unroll
        for (int ni = 0; ni < 4; ni++) {
            const int c = n0 + wn + ni * 8 + tc;
#pragma unroll
            for (int h = 0; h < 2; h++) {
                const int rr = r + h * 8;
                float v0 = acc[mi][ni][h * 2 + 0];
                float v1 = acc[mi][ni][h * 2 + 1];
                if (EPI == 1) {
                    v0 += colBias[c];
                    v1 += colBias[c + 1];
                } else if (EPI == 2) {
                    const float s = gamma[rr] * bnscale;
                    const float wb = rowBias[rr];
                    const float bt = beta[rr];
                    const float* rp = resid + (long)z * sR + (long)rr * N + c;
                    v0 = rp[0] + s * (v0 + wb) + bt;
                    v1 = rp[1] + s * (v1 + wb) + bt;
                }
                if constexpr (sizeof(OutT) == 2) {
                    __nv_bfloat162 p = __floats2bfloat162_rn(v0, v1);
                    *reinterpret_cast<__nv_bfloat162*>(
                        &((bf16*)(C + (long)z * sC))[(long)rr * N + c]) = p;
                } else {
                    float2 p = make_float2(v0, v1);
                    *reinterpret_cast<float2*>(
                        &((float*)(C + (long)z * sC))[(long)rr * N + c]) = p;
                }
            }
        }
    }
}

// ---------------------------------------------------------------------------
// Tiled transpose with dtype conversion: in (R,Cc) -> out (Cc,R) [ldOut], per z
// ---------------------------------------------------------------------------
__device__ __forceinline__ float ld_as_f(const float* p) { return *p; }
__device__ __forceinline__ float ld_as_f(const bf16* p) { return __bfloat162float(*p); }
__device__ __forceinline__ void st_from_f(float* p, float v) { *p = v; }
__device__ __forceinline__ void st_from_f(bf16* p, float v) { *p = __float2bfloat16(v); }

template <typename TI, typename TO>
__global__ void transpose_k(const TI* __restrict__ in, TO* __restrict__ out,
                            int R, int Cc, int ldOut, long sIn, long sOut) {
    __shared__ float tile[32][33];
    const TI* inb = in + (long)blockIdx.z * sIn;
    TO* outb = out + (long)blockIdx.z * sOut;
    const int c0 = blockIdx.x * 32;
    const int r0 = blockIdx.y * 32;
    const int tx = threadIdx.x, ty = threadIdx.y;
#pragma unroll
    for (int i = 0; i < 32; i += 8)
        tile[ty + i][tx] = ld_as_f(&inb[(long)(r0 + ty + i) * Cc + c0 + tx]);
    __syncthreads();
#pragma unroll
    for (int i = 0; i < 32; i += 8)
        st_from_f(&outb[(long)(c0 + ty + i) * ldOut + r0 + tx], tile[tx][ty + i]);
}

// ---------------------------------------------------------------------------
// fp32 -> bf16 elementwise convert
// ---------------------------------------------------------------------------
__global__ void f2bf_k(const float* __restrict__ in, bf16* __restrict__ out, int n) {
    const int i = blockIdx.x * 256 + threadIdx.x;
    if (i < n) out[i] = __float2bfloat16(in[i]);
}

// ---------------------------------------------------------------------------
// 2x2x2 max pool (bf16): conv (B,NPOS,Ci) -> out (B,outRows,Ci)
// ---------------------------------------------------------------------------
__global__ void pool_k(const bf16* __restrict__ conv, bf16* __restrict__ out,
                       int outRows) {
    const int ci = blockIdx.x * 256 + threadIdx.x;
    const int m = blockIdx.y;
    const int b = blockIdx.z;
    const int wp = m % WP;
    const int hp = (m / WP) % HP;
    const int tp = m / (WP * HP);
    const bf16* cb = conv + (long)b * NPOS * CI_DIM;
    const long n0 = (long)(2 * tp) * (H_DIM * W_DIM) + (long)(2 * hp) * W_DIM + 2 * wp;
    float mx = -INFINITY;
#pragma unroll
    for (int dt = 0; dt < 2; dt++)
#pragma unroll
        for (int dh = 0; dh < 2; dh++)
#pragma unroll
            for (int dw = 0; dw < 2; dw++) {
                long n = n0 + dt * (H_DIM * W_DIM) + dh * W_DIM + dw;
                mx = fmaxf(mx, __bfloat162float(cb[n * CI_DIM + ci]));
            }
    out[((long)b * outRows + m) * CI_DIM + ci] = __float2bfloat16(mx);
}

// ---------------------------------------------------------------------------
// In-place row softmax on bf16 logits (stride MPAD, MPOS valid); zeros the pads.
// ---------------------------------------------------------------------------
__global__ void __launch_bounds__(256) softmax_rows(bf16* __restrict__ f) {
    bf16* fr = f + (long)blockIdx.x * MPAD;
    const int t = threadIdx.x;
    float v[7];
    int cnt = 0;
    float mx = -1e30f;
    for (int i = t; i < MPOS; i += 256) {
        v[cnt] = __bfloat162float(fr[i]);
        mx = fmaxf(mx, v[cnt]);
        cnt++;
    }
    __shared__ float sred[8];
#pragma unroll
    for (int o = 16; o; o >>= 1) mx = fmaxf(mx, __shfl_xor_sync(0xffffffffu, mx, o));
    if ((t & 31) == 0) sred[t >> 5] = mx;
    __syncthreads();
    if (t < 32) {
        float m2 = (t < 8) ? sred[t] : -1e30f;
#pragma unroll
        for (int o = 4; o; o >>= 1) m2 = fmaxf(m2, __shfl_xor_sync(0xffffffffu, m2, o));
        if (t == 0) sred[0] = m2;
    }
    __syncthreads();
    mx = sred[0];
    float sum = 0.f;
    for (int j = 0; j < cnt; j++) {
        v[j] = __expf(v[j] - mx);
        sum += v[j];
    }
    __syncthreads();
#pragma unroll
    for (int o = 16; o; o >>= 1) sum += __shfl_xor_sync(0xffffffffu, sum, o);
    if ((t & 31) == 0) sred[t >> 5] = sum;
    __syncthreads();
    if (t < 32) {
        float s2 = (t < 8) ? sred[t] : 0.f;
#pragma unroll
        for (int o = 4; o; o >>= 1) s2 += __shfl_xor_sync(0xffffffffu, s2, o);
        if (t == 0) sred[0] = s2;
    }
    __syncthreads();
    const float inv = 1.0f / sred[0];
    int j = 0;
    for (int i = t; i < MPOS; i += 256) {
        fr[i] = __float2bfloat16(v[j] * inv);
        j++;
    }
    for (int i = MPOS + t; i < MPAD; i += 256) fr[i] = __float2bfloat16(0.f);
}

// ---------------------------------------------------------------------------
// Launch
// ---------------------------------------------------------------------------
extern "C" void kernel_launch(void* const* d_in, const int* in_sizes, int n_in,
                              void* d_out, int out_size) {
    (void)in_sizes; (void)n_in; (void)out_size;
    const float* x     = (const float*)d_in[0];
    const float* g_w   = (const float*)d_in[1];
    const float* g_b   = (const float*)d_in[2];
    const float* th_w  = (const float*)d_in[3];
    const float* th_b  = (const float*)d_in[4];
    const float* ph_w  = (const float*)d_in[5];
    const float* ph_b  = (const float*)d_in[6];
    const float* w_w   = (const float*)d_in[7];
    const float* w_b   = (const float*)d_in[8];
    const float* gamma = (const float*)d_in[9];
    const float* beta  = (const float*)d_in[10];
    float* out = (float*)d_out;

    bf16 *xT, *wbuf, *theta, *scr, *phi, *gmc, *gcm, *fbuf, *ybuf;
    cudaGetSymbolAddress((void**)&xT, d_xT);
    cudaGetSymbolAddress((void**)&wbuf, d_wbuf);
    cudaGetSymbolAddress((void**)&theta, d_theta);
    cudaGetSymbolAddress((void**)&scr, d_scr);
    cudaGetSymbolAddress((void**)&phi, d_phi);
    cudaGetSymbolAddress((void**)&gmc, d_gmc);
    cudaGetSymbolAddress((void**)&gcm, d_gcm);
    cudaGetSymbolAddress((void**)&fbuf, d_fbuf);
    cudaGetSymbolAddress((void**)&ybuf, d_ybuf);

    cudaFuncSetAttribute(mma_nt<1, bf16>, cudaFuncAttributeMaxDynamicSharedMemorySize, SMEM_MMA);
    cudaFuncSetAttribute(mma_nt<0, bf16>, cudaFuncAttributeMaxDynamicSharedMemorySize, SMEM_MMA);
    cudaFuncSetAttribute(mma_nt<2, float>, cudaFuncAttributeMaxDynamicSharedMemorySize, SMEM_MMA);

    bf16* th_wb = wbuf;
    bf16* ph_wb = wbuf + (size_t)CI_DIM * C_DIM;
    bf16* g_wb  = wbuf + (size_t)2 * CI_DIM * C_DIM;
    bf16* w_wb  = wbuf + (size_t)3 * CI_DIM * C_DIM;

    const long sX  = (long)C_DIM * NPOS;
    const long sXT = (long)NPOS * C_DIM;
    const long sTH = (long)NPOS * CI_DIM;
    const long sPH = (long)MPAD * CI_DIM;
    const long sGC = (long)CI_DIM * MPAD;
    const long sF  = (long)NPOS * MPAD;

    const int nw = CI_DIM * C_DIM;
    f2bf_k<<<(nw + 255) / 256, 256>>>(th_w, th_wb, nw);
    f2bf_k<<<(nw + 255) / 256, 256>>>(ph_w, ph_wb, nw);
    f2bf_k<<<(nw + 255) / 256, 256>>>(g_w, g_wb, nw);
    f2bf_k<<<(nw + 255) / 256, 256>>>(w_w, w_wb, nw);

    // 1) x (B,C,N) -> xT bf16 (B,N,C)
    transpose_k<float, bf16><<<dim3(NPOS / 32, C_DIM / 32, BATCH), dim3(32, 8)>>>(
        x, xT, C_DIM, NPOS, C_DIM, sX, sXT);

    const dim3 gConv(CI_DIM / 128, NPOS / 128, BATCH);

    // 2) theta conv
    mma_nt<1, bf16><<<gConv, 256, SMEM_MMA>>>(xT, th_wb, theta, NPOS, CI_DIM, C_DIM,
                                              sXT, 0, sTH, th_b, nullptr, nullptr,
                                              nullptr, nullptr, 0);
    // 3) g conv -> scr, pool -> gmc, transpose -> gcm (Ci,Mpad)
    mma_nt<1, bf16><<<gConv, 256, SMEM_MMA>>>(xT, g_wb, scr, NPOS, CI_DIM, C_DIM,
                                              sXT, 0, sTH, g_b, nullptr, nullptr,
                                              nullptr, nullptr, 0);
    pool_k<<<dim3(CI_DIM / 256, MPOS, BATCH), 256>>>(scr, gmc, MPOS);
    transpose_k<bf16, bf16><<<dim3(CI_DIM / 32, MPOS / 32, BATCH), dim3(32, 8)>>>(
        gmc, gcm, MPOS, CI_DIM, MPAD, (long)MPOS * CI_DIM, sGC);
    // 4) phi conv -> scr, pool -> phi (Mpad,Ci); pad rows stay zero
    mma_nt<1, bf16><<<gConv, 256, SMEM_MMA>>>(xT, ph_wb, scr, NPOS, CI_DIM, C_DIM,
                                              sXT, 0, sTH, ph_b, nullptr, nullptr,
                                              nullptr, nullptr, 0);
    pool_k<<<dim3(CI_DIM / 256, MPOS, BATCH), 256>>>(scr, phi, MPAD);

    // 5) f = theta @ phi^T -> bf16 logits (N,Mpad)
    mma_nt<0, bf16><<<dim3(MPAD / 128, NPOS / 128, BATCH), 256, SMEM_MMA>>>(
        theta, phi, fbuf, NPOS, MPAD, CI_DIM,
        sTH, sPH, sF, nullptr, nullptr, nullptr, nullptr, nullptr, 0);

    // 6) in-place softmax (bf16 logits -> bf16 probs, zeros in pads)
    softmax_rows<<<BATCH * NPOS, 256>>>(fbuf);

    // 7) y = p @ g : (N,Mpad)x(Ci,Mpad)^T -> bf16 (N,Ci)
    mma_nt<0, bf16><<<dim3(CI_DIM / 128, NPOS / 128, BATCH), 256, SMEM_MMA>>>(
        fbuf, gcm, ybuf, NPOS, CI_DIM, MPAD,
        sF, sGC, sTH, nullptr, nullptr, nullptr, nullptr, nullptr, 0);

    // 8) out(C,N) = x + scale*(w_w @ y^T + w_b) + beta
    mma_nt<2, float><<<dim3(NPOS / 128, C_DIM / 128, BATCH), 256, SMEM_MMA>>>(
        w_wb, ybuf, out, C_DIM, NPOS, CI_DIM,
        0, sTH, sX, nullptr, w_b, gamma, beta, x, sX);
}